// round 9
// baseline (speedup 1.0000x reference)
#include <cuda_runtime.h>
#include <cuda_bf16.h>
#include <cstdint>

// Problem constants
#define MDIM 16384
#define NDIM 16384
#define KDIM 512
#define ALPHA_C 0.1f
#define NU_C 1e-3f

#define MT 128
#define NT 128
#define UNIT_NT 16                  // N-tiles per work unit
#define UNITS_PER_M 8               // 128/16
#define UNITS_TOTAL 1024            // 128 m-tiles * 8
#define UPC 7                       // units per CTA (148*7 >= 1024)
#define GRID_MAIN 148

// smem layout (bytes)
#define SM_A   0                    // 8 chunks x [128 x 128B] SW128 = 131072
#define SM_B   131072               // 4-slot ring x 16384 = 65536
#define SM_M2  196608               // 2 x 128 floats = 1024
#define SM_STG 197632               // 128 rows x 24 floats = 12288
#define SMEM_BYTES 209920

// Scratch
__device__ __align__(16) __nv_bfloat16 g_A [MDIM * KDIM];
__device__ __align__(16) __nv_bfloat16 g_Bm[NDIM * KDIM];
__device__ float g_x2[MDIM];
__device__ float g_m2[NDIM];
__device__ float g_top6[UNITS_TOTAL * 128 * 6];   // per-unit per-row top-6 (3.1 MB)
__device__ float g_part[MDIM / MT];

// ---------------- PTX helpers ----------------
#define CP16(dst, src) \
  asm volatile("cp.async.cg.shared.global [%0], [%1], 16;\n" :: "r"(dst), "l"(src))
#define CP_COMMIT() asm volatile("cp.async.commit_group;\n" ::: "memory")
#define CP_WAIT(n)  asm volatile("cp.async.wait_group %0;\n" :: "n"(n) : "memory")

#define LDSM4(R0, R1, R2, R3, ADDR) \
  asm volatile("ldmatrix.sync.aligned.m8n8.x4.shared.b16 {%0,%1,%2,%3}, [%4];" \
               : "=r"(R0), "=r"(R1), "=r"(R2), "=r"(R3) : "r"(ADDR))

#define MMA16816(C, A, B0, B1) \
  asm volatile("mma.sync.aligned.m16n8k16.row.col.f32.bf16.bf16.f32 " \
               "{%0,%1,%2,%3},{%4,%5,%6,%7},{%8,%9},{%0,%1,%2,%3};" \
               : "+f"((C)[0]), "+f"((C)[1]), "+f"((C)[2]), "+f"((C)[3]) \
               : "r"((A)[0]), "r"((A)[1]), "r"((A)[2]), "r"((A)[3]), \
                 "r"(B0), "r"(B1))

#define SWZ128(x) ((x) ^ (((x) >> 3) & 0x70))

// ---------------- Prep kernels ----------------
__global__ void prep_phi(const float* __restrict__ phi) {
    __shared__ float t[32][33];
    int b = blockIdx.z, c0 = blockIdx.y * 32, h0 = blockIdx.x * 32;
    int tx = threadIdx.x, ty = threadIdx.y;
    const float* p = phi + ((size_t)b * 512 + c0) * 4096 + h0;
#pragma unroll
    for (int i = 0; i < 4; i++)
        t[ty + 8 * i][tx] = p[(size_t)(ty + 8 * i) * 4096 + tx];
    __syncthreads();
#pragma unroll
    for (int i = 0; i < 4; i++) {
        int row = ty + 8 * i;
        g_A[((size_t)b * 4096 + h0 + row) * 512 + c0 + tx] = __float2bfloat16(t[tx][row]);
    }
}

__global__ void prep_x2(const float* __restrict__ phi) {
    int m = blockIdx.x * 256 + threadIdx.x;
    int b = m >> 12, hw = m & 4095;
    const float* p = phi + (size_t)b * 512 * 4096 + hw;
    float s = 0.f;
#pragma unroll 8
    for (int c = 0; c < 512; c++) { float v = p[(size_t)c * 4096]; s = fmaf(v, v, s); }
    g_x2[m] = s;
}

__global__ void prep_mem(const float* __restrict__ mem) {
    int row  = (blockIdx.x * 256 + threadIdx.x) >> 5;
    int lane = threadIdx.x & 31;
    const float* p = mem + (size_t)row * 512;
    __nv_bfloat16* q = g_Bm + (size_t)row * 512;
    float s = 0.f;
#pragma unroll
    for (int i = 0; i < 16; i++) {
        float v = p[lane + i * 32];
        q[lane + i * 32] = __float2bfloat16(v);
        s = fmaf(v, v, s);
    }
#pragma unroll
    for (int o = 16; o > 0; o >>= 1) s += __shfl_xor_sync(0xffffffffu, s, o);
    if (lane == 0) g_m2[row] = s;
}

// ---------------- Main fused kernel ----------------
__device__ __forceinline__ void insert6a(float v, float (&q)[6]) {
    if (v < q[5]) {
        q[5] = v;
        if (q[5] < q[4]) { float t = q[4]; q[4] = q[5]; q[5] = t;
            if (q[4] < q[3]) { t = q[3]; q[3] = q[4]; q[4] = t;
                if (q[3] < q[2]) { t = q[2]; q[2] = q[3]; q[3] = t;
                    if (q[2] < q[1]) { t = q[1]; q[1] = q[2]; q[2] = t;
                        if (q[1] < q[0]) { t = q[0]; q[0] = q[1]; q[1] = t; } } } } }
    }
}

__device__ __forceinline__ void b_stage(uint32_t bOff, int slot, int n0, int s, int tid) {
#pragma unroll
    for (int i = 0; i < 2; i++) {
        int c = tid + i * 512;                // 1024 16B-units: 128 rows x 8 segs
        int row = c >> 3, seg = c & 7;
        uint32_t dst = bOff + (uint32_t)(slot * 16384 + SWZ128(row * 128 + seg * 16));
        CP16(dst, g_Bm + (size_t)(n0 + row) * KDIM + s * 64 + seg * 8);
    }
}

__global__ __launch_bounds__(512, 1)
void knn_gemm(const float* __restrict__ rptr) {
    extern __shared__ char smem[];
    float* m2s   = (float*)(smem + SM_M2);
    float* stage = (float*)(smem + SM_STG);
    (void)rptr;

    const int tid  = threadIdx.x;
    const int lane = tid & 31;
    const int warp = tid >> 5;
    const int wm   = warp & 3;     // 4 warps along M
    const int wn   = warp >> 2;    // 4 warps along N

    uint32_t sbase = (uint32_t)__cvta_generic_to_shared(smem);
    const uint32_t aOff = sbase + SM_A;
    const uint32_t bOff = sbase + SM_B;

    // ldmatrix lane mappings (verified R2/R4/R7/R8)
    const int aRow    = wm * 32 + (lane & 15);
    const int aColSel = ((lane >> 4) & 1) * 8;
    const int bRow    = wn * 32 + (lane & 7) + ((lane >> 4) & 1) * 8;
    const int bColSel = ((lane >> 3) & 1) * 8;

    const int g  = lane >> 2;
    const int qd = lane & 3;

    // unit range for this CTA
    const int u_begin = blockIdx.x * UPC;
    const int u_end_all = (u_begin + UPC < UNITS_TOTAL) ? u_begin + UPC : UNITS_TOTAL;
    if (u_begin >= UNITS_TOTAL) return;

    // running top-6 per (mi, p) row
    float ql[2][2][6];
#pragma unroll
    for (int mi = 0; mi < 2; mi++)
#pragma unroll
        for (int p = 0; p < 2; p++)
#pragma unroll
            for (int j = 0; j < 6; j++) ql[mi][p][j] = INFINITY;

    float acc[2][4][4];
#pragma unroll
    for (int mi = 0; mi < 2; mi++)
#pragma unroll
        for (int ni = 0; ni < 4; ni++)
#pragma unroll
            for (int r = 0; r < 4; r++) acc[mi][ni][r] = 0.f;

    int ug = u_begin;
#pragma unroll 1
    while (ug < u_end_all) {
        const int m    = ug >> 3;                       // m-tile
        const int uend = ((m + 1) * UNITS_PER_M < u_end_all) ? (m + 1) * UNITS_PER_M : u_end_all;
        const int m0   = m * MT;
        const int nt_begin = (ug - m * UNITS_PER_M) * UNIT_NT;
        const int nloc_tiles = (uend - ug) * UNIT_NT;
        const int nstages = nloc_tiles * 8;

        __syncthreads();   // protect A region: all warps done with previous group

        float x2v[2][2];
#pragma unroll
        for (int mi = 0; mi < 2; mi++)
#pragma unroll
            for (int p = 0; p < 2; p++)
                x2v[mi][p] = g_x2[m0 + wm * 32 + mi * 16 + g + p * 8];

        // ---- resident A load for this m: 8 chunks x [128 x 128B] SW128
#pragma unroll
        for (int i = 0; i < 16; i++) {
            int c = tid + i * 512;
            int chunk = c >> 10, u = c & 1023;
            int row = u >> 3, seg = u & 7;
            uint32_t dst = aOff + (uint32_t)(chunk * 16384 + SWZ128(row * 128 + seg * 16));
            CP16(dst, g_A + (size_t)(m0 + row) * KDIM + chunk * 64 + seg * 8);
        }
        CP_COMMIT();
        // ---- B ring prologue: stages 0,1,2 of this group
        b_stage(bOff, 0, (nt_begin + 0) * NT, 0, tid); CP_COMMIT();
        b_stage(bOff, 1, (nt_begin + 0) * NT, 1, tid); CP_COMMIT();
        b_stage(bOff, 2, (nt_begin + 0) * NT, 2, tid); CP_COMMIT();

#pragma unroll 1
        for (int gg = 0; gg < nstages; gg++) {
            const int s   = gg & 7;
            const int ntl = gg >> 3;                    // local tile idx in group
            const int nt  = nt_begin + ntl;
            const int mb  = ntl & 1;

            if (s == 0 && tid < 128) m2s[mb * 128 + tid] = g_m2[nt * NT + tid];

            CP_WAIT(2);
            __syncthreads();

            const uint32_t bbuf = bOff + (gg & 3) * 16384;
            const uint32_t abuf = aOff + s * 16384;
#pragma unroll
            for (int kk = 0; kk < 64; kk += 16) {
                uint32_t a[2][4], bf[4][2];
#pragma unroll
                for (int mi = 0; mi < 2; mi++) {
                    uint32_t ad = abuf + (uint32_t)SWZ128(((aRow + mi * 16) * 128 + (kk + aColSel) * 2));
                    LDSM4(a[mi][0], a[mi][1], a[mi][2], a[mi][3], ad);
                }
#pragma unroll
                for (int jp = 0; jp < 2; jp++) {
                    uint32_t bd = bbuf + (uint32_t)SWZ128(((bRow + jp * 16) * 128 + (kk + bColSel) * 2));
                    LDSM4(bf[2 * jp][0], bf[2 * jp][1], bf[2 * jp + 1][0], bf[2 * jp + 1][1], bd);
                }
#pragma unroll
                for (int mi = 0; mi < 2; mi++)
#pragma unroll
                    for (int ni = 0; ni < 4; ni++)
                        MMA16816(acc[mi][ni], a[mi], bf[ni][0], bf[ni][1]);
            }

            // keep the ring rolling within the group (always commit)
            const int g3 = gg + 3;
            if (g3 < nstages)
                b_stage(bOff, g3 & 3, (nt_begin + (g3 >> 3)) * NT, g3 & 7, tid);
            CP_COMMIT();

            if (s == 7) {
                // in-register epilogue: 16 distances into 4 running lists
#pragma unroll
                for (int mi = 0; mi < 2; mi++)
#pragma unroll
                    for (int ni = 0; ni < 4; ni++) {
                        const int col = wn * 32 + ni * 8 + 2 * qd;
                        const float m20 = m2s[mb * 128 + col];
                        const float m21 = m2s[mb * 128 + col + 1];
                        insert6a(fmaxf(fmaf(-2.f, acc[mi][ni][0], x2v[mi][0] + m20), 0.f), ql[mi][0]);
                        insert6a(fmaxf(fmaf(-2.f, acc[mi][ni][1], x2v[mi][0] + m21), 0.f), ql[mi][0]);
                        insert6a(fmaxf(fmaf(-2.f, acc[mi][ni][2], x2v[mi][1] + m20), 0.f), ql[mi][1]);
                        insert6a(fmaxf(fmaf(-2.f, acc[mi][ni][3], x2v[mi][1] + m21), 0.f), ql[mi][1]);
                        acc[mi][ni][0] = 0.f; acc[mi][ni][1] = 0.f;
                        acc[mi][ni][2] = 0.f; acc[mi][ni][3] = 0.f;
                    }

                if ((ntl & (UNIT_NT - 1)) == UNIT_NT - 1) {
                    // ===== unit boundary: merge + flush + reset (uniform branch) =====
                    const int uu = ug + (ntl >> 4);     // global unit index
                    // quad merge, snapshot-before-insert
#pragma unroll
                    for (int off = 2; off > 0; off >>= 1) {
#pragma unroll
                        for (int mi = 0; mi < 2; mi++)
#pragma unroll
                            for (int p = 0; p < 2; p++) {
                                float t[6];
#pragma unroll
                                for (int j = 0; j < 6; j++)
                                    t[j] = __shfl_down_sync(0xffffffffu, ql[mi][p][j], off, 4);
#pragma unroll
                                for (int j = 0; j < 6; j++) insert6a(t[j], ql[mi][p]);
                            }
                    }
                    if (qd == 0) {
#pragma unroll
                        for (int mi = 0; mi < 2; mi++)
#pragma unroll
                            for (int p = 0; p < 2; p++) {
                                int r = wm * 32 + mi * 16 + g + p * 8;
#pragma unroll
                                for (int j = 0; j < 6; j++)
                                    stage[r * 24 + wn * 6 + j] = ql[mi][p][j];
                            }
                    }
                    __syncthreads();
                    if (tid < 128) {
                        float f[6] = {INFINITY, INFINITY, INFINITY, INFINITY, INFINITY, INFINITY};
                        const float* sr = stage + tid * 24;
#pragma unroll
                        for (int i = 0; i < 24; i++) insert6a(sr[i], f);
                        float* dst = g_top6 + ((size_t)uu * 128 + tid) * 6;
#pragma unroll
                        for (int j = 0; j < 6; j++) dst[j] = f[j];
                    }
                    __syncthreads();
                    // reset lists for next unit
#pragma unroll
                    for (int mi = 0; mi < 2; mi++)
#pragma unroll
                        for (int p = 0; p < 2; p++)
#pragma unroll
                            for (int j = 0; j < 6; j++) ql[mi][p][j] = INFINITY;
                }
            }
        }
        ug = uend;
    }
}

// Merge 8 unit-partials per row, hinge, per-m-tile reduce
__global__ void finalize_top(const float* __restrict__ rptr) {
    __shared__ float red[128];
    const int b = blockIdx.x;     // m-tile
    const int t = threadIdx.x;    // row
    float f[6] = {INFINITY, INFINITY, INFINITY, INFINITY, INFINITY, INFINITY};
    const float* base = g_top6 + ((size_t)b * UNITS_PER_M * 128 + t) * 6;
#pragma unroll
    for (int j = 0; j < UNITS_PER_M; j++) {
        const float* src = base + (size_t)j * 128 * 6;
#pragma unroll
        for (int k = 0; k < 6; k++) insert6a(src[k], f);
    }
    float rv = rptr[0];
    float r2 = rv * rv;
    float part = fmaxf(f[0] - r2, 0.f) + fmaxf(f[1] - r2, 0.f) + fmaxf(f[2] - r2, 0.f)
               + fmaxf(r2 - f[3] - ALPHA_C, 0.f) + fmaxf(r2 - f[4] - ALPHA_C, 0.f)
               + fmaxf(r2 - f[5] - ALPHA_C, 0.f);
    red[t] = part;
    __syncthreads();
#pragma unroll
    for (int o = 64; o > 0; o >>= 1) {
        if (t < o) red[t] += red[t + o];
        __syncthreads();
    }
    if (t == 0) g_part[b] = red[0];
}

// Deterministic final reduction
__global__ void finalize_loss(float* __restrict__ out) {
    __shared__ float s[128];
    int t = threadIdx.x;
    s[t] = g_part[t];
    __syncthreads();
#pragma unroll
    for (int o = 64; o > 0; o >>= 1) {
        if (t < o) s[t] += s[t + o];
        __syncthreads();
    }
    if (t == 0) out[0] = s[0] * (1.0f / (49152.0f * NU_C));
}

// ---------------- launch ----------------
extern "C" void kernel_launch(void* const* d_in, const int* in_sizes, int n_in,
                              void* d_out, int out_size) {
    (void)in_sizes; (void)n_in; (void)out_size;
    const float* phi = (const float*)d_in[0];
    const float* mem = (const float*)d_in[1];
    const float* r   = (const float*)d_in[2];
    float* out = (float*)d_out;

    cudaFuncSetAttribute(knn_gemm, cudaFuncAttributeMaxDynamicSharedMemorySize, SMEM_BYTES);

    prep_phi<<<dim3(128, 16, 4), dim3(32, 8)>>>(phi);
    prep_x2<<<MDIM / 256, 256>>>(phi);
    prep_mem<<<NDIM / 8, 256>>>(mem);
    knn_gemm<<<GRID_MAIN, 512, SMEM_BYTES>>>(r);
    finalize_top<<<MDIM / MT, 128>>>(r);
    finalize_loss<<<1, 128>>>(out);
}

// round 10
// speedup vs baseline: 1.0176x; 1.0176x over previous
#include <cuda_runtime.h>
#include <cuda_bf16.h>
#include <cstdint>

// Problem constants
#define MDIM 16384
#define NDIM 16384
#define KDIM 512
#define ALPHA_C 0.1f
#define NU_C 1e-3f

#define MT 128
#define NT 128
#define UNIT_NT 16                  // N-tiles per work unit
#define UNIT_STAGES 128             // UNIT_NT * 8 (compile-time inner loop)
#define UNITS_PER_M 8               // 128/16
#define UNITS_TOTAL 1024            // 128 m-tiles * 8
#define UPC 7                       // units per CTA (148*7 >= 1024)
#define GRID_MAIN 148

// smem layout (bytes)
#define SM_A   0                    // 8 chunks x [128 x 128B] SW128 = 131072
#define SM_B   131072               // 4-slot ring x 16384 = 65536
#define SM_M2  196608               // 2 x 128 floats = 1024
#define SM_STG 197632               // 128 rows x 24 floats = 12288
#define SMEM_BYTES 209920

// Scratch
__device__ __align__(16) __nv_bfloat16 g_A [MDIM * KDIM];
__device__ __align__(16) __nv_bfloat16 g_Bm[NDIM * KDIM];
__device__ float g_x2[MDIM];
__device__ float g_m2[NDIM];
__device__ float g_top6[UNITS_TOTAL * 128 * 6];   // per-unit per-row top-6
__device__ float g_part[MDIM / MT];

// ---------------- PTX helpers ----------------
#define CP16(dst, src) \
  asm volatile("cp.async.cg.shared.global [%0], [%1], 16;\n" :: "r"(dst), "l"(src))
#define CP_COMMIT() asm volatile("cp.async.commit_group;\n" ::: "memory")
#define CP_WAIT(n)  asm volatile("cp.async.wait_group %0;\n" :: "n"(n) : "memory")

#define LDSM4(R0, R1, R2, R3, ADDR) \
  asm volatile("ldmatrix.sync.aligned.m8n8.x4.shared.b16 {%0,%1,%2,%3}, [%4];" \
               : "=r"(R0), "=r"(R1), "=r"(R2), "=r"(R3) : "r"(ADDR))

#define MMA16816(C, A, B0, B1) \
  asm volatile("mma.sync.aligned.m16n8k16.row.col.f32.bf16.bf16.f32 " \
               "{%0,%1,%2,%3},{%4,%5,%6,%7},{%8,%9},{%0,%1,%2,%3};" \
               : "+f"((C)[0]), "+f"((C)[1]), "+f"((C)[2]), "+f"((C)[3]) \
               : "r"((A)[0]), "r"((A)[1]), "r"((A)[2]), "r"((A)[3]), \
                 "r"(B0), "r"(B1))

#define SWZ128(x) ((x) ^ (((x) >> 3) & 0x70))

// ---------------- Prep kernels ----------------
__global__ void prep_phi(const float* __restrict__ phi) {
    __shared__ float t[32][33];
    int b = blockIdx.z, c0 = blockIdx.y * 32, h0 = blockIdx.x * 32;
    int tx = threadIdx.x, ty = threadIdx.y;
    const float* p = phi + ((size_t)b * 512 + c0) * 4096 + h0;
#pragma unroll
    for (int i = 0; i < 4; i++)
        t[ty + 8 * i][tx] = p[(size_t)(ty + 8 * i) * 4096 + tx];
    __syncthreads();
#pragma unroll
    for (int i = 0; i < 4; i++) {
        int row = ty + 8 * i;
        g_A[((size_t)b * 4096 + h0 + row) * 512 + c0 + tx] = __float2bfloat16(t[tx][row]);
    }
}

__global__ void prep_x2(const float* __restrict__ phi) {
    int m = blockIdx.x * 256 + threadIdx.x;
    int b = m >> 12, hw = m & 4095;
    const float* p = phi + (size_t)b * 512 * 4096 + hw;
    float s = 0.f;
#pragma unroll 8
    for (int c = 0; c < 512; c++) { float v = p[(size_t)c * 4096]; s = fmaf(v, v, s); }
    g_x2[m] = s;
}

__global__ void prep_mem(const float* __restrict__ mem) {
    int row  = (blockIdx.x * 256 + threadIdx.x) >> 5;
    int lane = threadIdx.x & 31;
    const float* p = mem + (size_t)row * 512;
    __nv_bfloat16* q = g_Bm + (size_t)row * 512;
    float s = 0.f;
#pragma unroll
    for (int i = 0; i < 16; i++) {
        float v = p[lane + i * 32];
        q[lane + i * 32] = __float2bfloat16(v);
        s = fmaf(v, v, s);
    }
#pragma unroll
    for (int o = 16; o > 0; o >>= 1) s += __shfl_xor_sync(0xffffffffu, s, o);
    if (lane == 0) g_m2[row] = s;
}

// ---------------- Main fused kernel ----------------
__device__ __forceinline__ void insert6a(float v, float (&q)[6]) {
    if (v < q[5]) {
        q[5] = v;
        if (q[5] < q[4]) { float t = q[4]; q[4] = q[5]; q[5] = t;
            if (q[4] < q[3]) { t = q[3]; q[3] = q[4]; q[4] = t;
                if (q[3] < q[2]) { t = q[2]; q[2] = q[3]; q[3] = t;
                    if (q[2] < q[1]) { t = q[1]; q[1] = q[2]; q[2] = t;
                        if (q[1] < q[0]) { t = q[0]; q[0] = q[1]; q[1] = t; } } } } }
    }
}

__device__ __forceinline__ void b_stage(uint32_t bOff, int slot, int n0, int s, int tid) {
#pragma unroll
    for (int i = 0; i < 2; i++) {
        int c = tid + i * 512;                // 1024 16B-units: 128 rows x 8 segs
        int row = c >> 3, seg = c & 7;
        uint32_t dst = bOff + (uint32_t)(slot * 16384 + SWZ128(row * 128 + seg * 16));
        CP16(dst, g_Bm + (size_t)(n0 + row) * KDIM + s * 64 + seg * 8);
    }
}

__global__ __launch_bounds__(512, 1)
void knn_gemm(const float* __restrict__ rptr) {
    extern __shared__ char smem[];
    float* m2s   = (float*)(smem + SM_M2);
    float* stage = (float*)(smem + SM_STG);
    (void)rptr;

    const int tid  = threadIdx.x;
    const int lane = tid & 31;
    const int warp = tid >> 5;
    const int wm   = warp & 3;     // 4 warps along M
    const int wn   = warp >> 2;    // 4 warps along N

    uint32_t sbase = (uint32_t)__cvta_generic_to_shared(smem);
    const uint32_t aOff = sbase + SM_A;
    const uint32_t bOff = sbase + SM_B;

    // ldmatrix lane mappings (verified R2/R4/R7/R8)
    const int aRow    = wm * 32 + (lane & 15);
    const int aColSel = ((lane >> 4) & 1) * 8;
    const int bRow    = wn * 32 + (lane & 7) + ((lane >> 4) & 1) * 8;
    const int bColSel = ((lane >> 3) & 1) * 8;

    const int g  = lane >> 2;
    const int qd = lane & 3;

    const int u_begin = blockIdx.x * UPC;
    const int u_end = (u_begin + UPC < UNITS_TOTAL) ? u_begin + UPC : UNITS_TOTAL;
    if (u_begin >= UNITS_TOTAL) return;

    float ql[2][2][6];
#pragma unroll
    for (int mi = 0; mi < 2; mi++)
#pragma unroll
        for (int p = 0; p < 2; p++)
#pragma unroll
            for (int j = 0; j < 6; j++) ql[mi][p][j] = INFINITY;

    float acc[2][4][4];
#pragma unroll
    for (int mi = 0; mi < 2; mi++)
#pragma unroll
        for (int ni = 0; ni < 4; ni++)
#pragma unroll
            for (int r = 0; r < 4; r++) acc[mi][ni][r] = 0.f;

    float x2v[2][2];
    int prev_m = -1;

#pragma unroll 1
    for (int ug = u_begin; ug < u_end; ug++) {
        const int m  = ug >> 3;
        const int m0 = m * MT;
        const int n_base = (ug & 7) * UNIT_NT * NT;   // first column of this unit

        if (m != prev_m) {
            // A region rewrite: all warps have passed the previous unit's flush syncs
#pragma unroll
            for (int i = 0; i < 16; i++) {
                int c = tid + i * 512;
                int chunk = c >> 10, u = c & 1023;
                int row = u >> 3, seg = u & 7;
                uint32_t dst = aOff + (uint32_t)(chunk * 16384 + SWZ128(row * 128 + seg * 16));
                CP16(dst, g_A + (size_t)(m0 + row) * KDIM + chunk * 64 + seg * 8);
            }
            CP_COMMIT();
#pragma unroll
            for (int mi = 0; mi < 2; mi++)
#pragma unroll
                for (int p = 0; p < 2; p++)
                    x2v[mi][p] = g_x2[m0 + wm * 32 + mi * 16 + g + p * 8];
            prev_m = m;
        }
        // B ring prologue for this unit
        b_stage(bOff, 0, n_base, 0, tid); CP_COMMIT();
        b_stage(bOff, 1, n_base, 1, tid); CP_COMMIT();
        b_stage(bOff, 2, n_base, 2, tid); CP_COMMIT();

        // ---- compile-time 128-stage inner loop ----
#pragma unroll 1
        for (int gg = 0; gg < UNIT_STAGES; gg++) {
            const int s   = gg & 7;
            const int ntl = gg >> 3;
            const int mb  = ntl & 1;

            if (s == 0 && tid < 128) m2s[mb * 128 + tid] = g_m2[n_base + ntl * NT + tid];

            CP_WAIT(2);
            __syncthreads();

            const uint32_t bbuf = bOff + (gg & 3) * 16384;
            const uint32_t abuf = aOff + s * 16384;
#pragma unroll
            for (int kk = 0; kk < 64; kk += 16) {
                uint32_t a[2][4], bf[4][2];
#pragma unroll
                for (int mi = 0; mi < 2; mi++) {
                    uint32_t ad = abuf + (uint32_t)SWZ128(((aRow + mi * 16) * 128 + (kk + aColSel) * 2));
                    LDSM4(a[mi][0], a[mi][1], a[mi][2], a[mi][3], ad);
                }
#pragma unroll
                for (int jp = 0; jp < 2; jp++) {
                    uint32_t bd = bbuf + (uint32_t)SWZ128(((bRow + jp * 16) * 128 + (kk + bColSel) * 2));
                    LDSM4(bf[2 * jp][0], bf[2 * jp][1], bf[2 * jp + 1][0], bf[2 * jp + 1][1], bd);
                }
#pragma unroll
                for (int mi = 0; mi < 2; mi++)
#pragma unroll
                    for (int ni = 0; ni < 4; ni++)
                        MMA16816(acc[mi][ni], a[mi], bf[ni][0], bf[ni][1]);
            }

            const int g3 = gg + 3;
            if (g3 < UNIT_STAGES)
                b_stage(bOff, g3 & 3, n_base + (g3 >> 3) * NT, g3 & 7, tid);
            CP_COMMIT();

            if (s == 7) {
#pragma unroll
                for (int mi = 0; mi < 2; mi++)
#pragma unroll
                    for (int ni = 0; ni < 4; ni++) {
                        const int col = wn * 32 + ni * 8 + 2 * qd;
                        const float m20 = m2s[mb * 128 + col];
                        const float m21 = m2s[mb * 128 + col + 1];
                        insert6a(fmaxf(fmaf(-2.f, acc[mi][ni][0], x2v[mi][0] + m20), 0.f), ql[mi][0]);
                        insert6a(fmaxf(fmaf(-2.f, acc[mi][ni][1], x2v[mi][0] + m21), 0.f), ql[mi][0]);
                        insert6a(fmaxf(fmaf(-2.f, acc[mi][ni][2], x2v[mi][1] + m20), 0.f), ql[mi][1]);
                        insert6a(fmaxf(fmaf(-2.f, acc[mi][ni][3], x2v[mi][1] + m21), 0.f), ql[mi][1]);
                        acc[mi][ni][0] = 0.f; acc[mi][ni][1] = 0.f;
                        acc[mi][ni][2] = 0.f; acc[mi][ni][3] = 0.f;
                    }
            }
        }

        // ===== unit flush: quad merge + stage + write g_top6[ug], reset =====
#pragma unroll
        for (int off = 2; off > 0; off >>= 1) {
#pragma unroll
            for (int mi = 0; mi < 2; mi++)
#pragma unroll
                for (int p = 0; p < 2; p++) {
                    float t[6];
#pragma unroll
                    for (int j = 0; j < 6; j++)
                        t[j] = __shfl_down_sync(0xffffffffu, ql[mi][p][j], off, 4);
#pragma unroll
                    for (int j = 0; j < 6; j++) insert6a(t[j], ql[mi][p]);
                }
        }
        if (qd == 0) {
#pragma unroll
            for (int mi = 0; mi < 2; mi++)
#pragma unroll
                for (int p = 0; p < 2; p++) {
                    int r = wm * 32 + mi * 16 + g + p * 8;
#pragma unroll
                    for (int j = 0; j < 6; j++)
                        stage[r * 24 + wn * 6 + j] = ql[mi][p][j];
                }
        }
        __syncthreads();
        if (tid < 128) {
            float f[6] = {INFINITY, INFINITY, INFINITY, INFINITY, INFINITY, INFINITY};
            const float* sr = stage + tid * 24;
#pragma unroll
            for (int i = 0; i < 24; i++) insert6a(sr[i], f);
            float* dst = g_top6 + ((size_t)ug * 128 + tid) * 6;
#pragma unroll
            for (int j = 0; j < 6; j++) dst[j] = f[j];
        }
        __syncthreads();
#pragma unroll
        for (int mi = 0; mi < 2; mi++)
#pragma unroll
            for (int p = 0; p < 2; p++)
#pragma unroll
                for (int j = 0; j < 6; j++) ql[mi][p][j] = INFINITY;
    }
}

// Merge 8 unit-partials per row, hinge, per-m-tile reduce
__global__ void finalize_top(const float* __restrict__ rptr) {
    __shared__ float red[128];
    const int b = blockIdx.x;     // m-tile
    const int t = threadIdx.x;    // row
    float f[6] = {INFINITY, INFINITY, INFINITY, INFINITY, INFINITY, INFINITY};
    const float* base = g_top6 + ((size_t)b * UNITS_PER_M * 128 + t) * 6;
#pragma unroll
    for (int j = 0; j < UNITS_PER_M; j++) {
        const float* src = base + (size_t)j * 128 * 6;
#pragma unroll
        for (int k = 0; k < 6; k++) insert6a(src[k], f);
    }
    float rv = rptr[0];
    float r2 = rv * rv;
    float part = fmaxf(f[0] - r2, 0.f) + fmaxf(f[1] - r2, 0.f) + fmaxf(f[2] - r2, 0.f)
               + fmaxf(r2 - f[3] - ALPHA_C, 0.f) + fmaxf(r2 - f[4] - ALPHA_C, 0.f)
               + fmaxf(r2 - f[5] - ALPHA_C, 0.f);
    red[t] = part;
    __syncthreads();
#pragma unroll
    for (int o = 64; o > 0; o >>= 1) {
        if (t < o) red[t] += red[t + o];
        __syncthreads();
    }
    if (t == 0) g_part[b] = red[0];
}

// Deterministic final reduction
__global__ void finalize_loss(float* __restrict__ out) {
    __shared__ float s[128];
    int t = threadIdx.x;
    s[t] = g_part[t];
    __syncthreads();
#pragma unroll
    for (int o = 64; o > 0; o >>= 1) {
        if (t < o) s[t] += s[t + o];
        __syncthreads();
    }
    if (t == 0) out[0] = s[0] * (1.0f / (49152.0f * NU_C));
}

// ---------------- launch ----------------
extern "C" void kernel_launch(void* const* d_in, const int* in_sizes, int n_in,
                              void* d_out, int out_size) {
    (void)in_sizes; (void)n_in; (void)out_size;
    const float* phi = (const float*)d_in[0];
    const float* mem = (const float*)d_in[1];
    const float* r   = (const float*)d_in[2];
    float* out = (float*)d_out;

    cudaFuncSetAttribute(knn_gemm, cudaFuncAttributeMaxDynamicSharedMemorySize, SMEM_BYTES);

    prep_phi<<<dim3(128, 16, 4), dim3(32, 8)>>>(phi);
    prep_x2<<<MDIM / 256, 256>>>(phi);
    prep_mem<<<NDIM / 8, 256>>>(mem);
    knn_gemm<<<GRID_MAIN, 512, SMEM_BYTES>>>(r);
    finalize_top<<<MDIM / MT, 128>>>(r);
    finalize_loss<<<1, 128>>>(out);
}

// round 11
// speedup vs baseline: 1.2467x; 1.2250x over previous
#include <cuda_runtime.h>
#include <cuda_bf16.h>
#include <cstdint>

// Problem constants
#define MDIM 16384
#define NDIM 16384
#define KDIM 512
#define ALPHA_C 0.1f
#define NU_C 1e-3f

#define MT 128
#define NT 128
#define NTILES (NDIM / NT)          // 128

// smem layout (bytes)
#define SM_A   0                    // 8 chunks x [128 x 128B] SW128 = 131072
#define SM_B   131072               // 4-slot ring x 16384 = 65536
#define SM_M2  196608               // 2 x 128 floats = 1024
#define SM_STG 197632               // 128 rows x 24 floats = 12288 (also reduce scratch)
#define SMEM_BYTES 209920

// Scratch
__device__ __align__(16) __nv_bfloat16 g_A [MDIM * KDIM];
__device__ __align__(16) __nv_bfloat16 g_Bm[NDIM * KDIM];
__device__ float g_x2[MDIM];
__device__ float g_m2[NDIM];
__device__ float g_part[MDIM / MT];

// ---------------- PTX helpers ----------------
#define CP16(dst, src) \
  asm volatile("cp.async.cg.shared.global [%0], [%1], 16;\n" :: "r"(dst), "l"(src))
#define CP_COMMIT() asm volatile("cp.async.commit_group;\n" ::: "memory")
#define CP_WAIT(n)  asm volatile("cp.async.wait_group %0;\n" :: "n"(n) : "memory")

#define LDSM4(R0, R1, R2, R3, ADDR) \
  asm volatile("ldmatrix.sync.aligned.m8n8.x4.shared.b16 {%0,%1,%2,%3}, [%4];" \
               : "=r"(R0), "=r"(R1), "=r"(R2), "=r"(R3) : "r"(ADDR))

#define MMA16816(C, A, B0, B1) \
  asm volatile("mma.sync.aligned.m16n8k16.row.col.f32.bf16.bf16.f32 " \
               "{%0,%1,%2,%3},{%4,%5,%6,%7},{%8,%9},{%0,%1,%2,%3};" \
               : "+f"((C)[0]), "+f"((C)[1]), "+f"((C)[2]), "+f"((C)[3]) \
               : "r"((A)[0]), "r"((A)[1]), "r"((A)[2]), "r"((A)[3]), \
                 "r"(B0), "r"(B1))

#define SWZ128(x) ((x) ^ (((x) >> 3) & 0x70))

// ---------------- Prep kernels ----------------
__global__ void prep_phi(const float* __restrict__ phi) {
    __shared__ float t[32][33];
    int b = blockIdx.z, c0 = blockIdx.y * 32, h0 = blockIdx.x * 32;
    int tx = threadIdx.x, ty = threadIdx.y;
    const float* p = phi + ((size_t)b * 512 + c0) * 4096 + h0;
#pragma unroll
    for (int i = 0; i < 4; i++)
        t[ty + 8 * i][tx] = p[(size_t)(ty + 8 * i) * 4096 + tx];
    __syncthreads();
#pragma unroll
    for (int i = 0; i < 4; i++) {
        int row = ty + 8 * i;
        g_A[((size_t)b * 4096 + h0 + row) * 512 + c0 + tx] = __float2bfloat16(t[tx][row]);
    }
}

__global__ void prep_x2(const float* __restrict__ phi) {
    int m = blockIdx.x * 256 + threadIdx.x;
    int b = m >> 12, hw = m & 4095;
    const float* p = phi + (size_t)b * 512 * 4096 + hw;
    float s = 0.f;
#pragma unroll 8
    for (int c = 0; c < 512; c++) { float v = p[(size_t)c * 4096]; s = fmaf(v, v, s); }
    g_x2[m] = s;
}

__global__ void prep_mem(const float* __restrict__ mem) {
    int row  = (blockIdx.x * 256 + threadIdx.x) >> 5;
    int lane = threadIdx.x & 31;
    const float* p = mem + (size_t)row * 512;
    __nv_bfloat16* q = g_Bm + (size_t)row * 512;
    float s = 0.f;
#pragma unroll
    for (int i = 0; i < 16; i++) {
        float v = p[lane + i * 32];
        q[lane + i * 32] = __float2bfloat16(v);
        s = fmaf(v, v, s);
    }
#pragma unroll
    for (int o = 16; o > 0; o >>= 1) s += __shfl_xor_sync(0xffffffffu, s, o);
    if (lane == 0) g_m2[row] = s;
}

// ---------------- Main fused kernel ----------------
__device__ __forceinline__ void insert6a(float v, float (&q)[6]) {
    if (v < q[5]) {
        q[5] = v;
        if (q[5] < q[4]) { float t = q[4]; q[4] = q[5]; q[5] = t;
            if (q[4] < q[3]) { t = q[3]; q[3] = q[4]; q[4] = t;
                if (q[3] < q[2]) { t = q[2]; q[2] = q[3]; q[3] = t;
                    if (q[2] < q[1]) { t = q[1]; q[1] = q[2]; q[2] = t;
                        if (q[1] < q[0]) { t = q[0]; q[0] = q[1]; q[1] = t; } } } } }
    }
}

__device__ __forceinline__ void b_stage(uint32_t bOff, int slot, int n0, int s, int tid) {
#pragma unroll
    for (int i = 0; i < 2; i++) {
        int c = tid + i * 512;                // 1024 16B-units: 128 rows x 8 segs
        int row = c >> 3, seg = c & 7;
        uint32_t dst = bOff + (uint32_t)(slot * 16384 + SWZ128(row * 128 + seg * 16));
        CP16(dst, g_Bm + (size_t)(n0 + row) * KDIM + s * 64 + seg * 8);
    }
}

__global__ __launch_bounds__(512, 1)
void knn_gemm(const float* __restrict__ rptr) {
    extern __shared__ char smem[];
    float* m2s   = (float*)(smem + SM_M2);
    float* stage = (float*)(smem + SM_STG);

    const int tid  = threadIdx.x;
    const int lane = tid & 31;
    const int warp = tid >> 5;
    const int wm   = warp & 3;     // 4 warps along M
    const int wn   = warp >> 2;    // 4 warps along N
    const int m0   = blockIdx.x * MT;

    uint32_t sbase = (uint32_t)__cvta_generic_to_shared(smem);
    const uint32_t aOff = sbase + SM_A;
    const uint32_t bOff = sbase + SM_B;

    // ldmatrix lane mappings (verified R2/R4/R7/R8)
    const int aRow    = wm * 32 + (lane & 15);
    const int aColSel = ((lane >> 4) & 1) * 8;
    const int bRow    = wn * 32 + (lane & 7) + ((lane >> 4) & 1) * 8;
    const int bColSel = ((lane >> 3) & 1) * 8;

    const int g  = lane >> 2;
    const int qd = lane & 3;

    float x2v[2][2];
#pragma unroll
    for (int mi = 0; mi < 2; mi++)
#pragma unroll
        for (int p = 0; p < 2; p++)
            x2v[mi][p] = g_x2[m0 + wm * 32 + mi * 16 + g + p * 8];

    // ---- resident A load: 8 chunks x [128 x 128B] SW128 (full K)
#pragma unroll
    for (int i = 0; i < 16; i++) {
        int c = tid + i * 512;
        int chunk = c >> 10, u = c & 1023;
        int row = u >> 3, seg = u & 7;
        uint32_t dst = aOff + (uint32_t)(chunk * 16384 + SWZ128(row * 128 + seg * 16));
        CP16(dst, g_A + (size_t)(m0 + row) * KDIM + chunk * 64 + seg * 8);
    }
    CP_COMMIT();
    // ---- B ring prologue: stages 0,1,2 (prefetch distance 3)
    b_stage(bOff, 0, 0, 0, tid); CP_COMMIT();
    b_stage(bOff, 1, 0, 1, tid); CP_COMMIT();
    b_stage(bOff, 2, 0, 2, tid); CP_COMMIT();

    float ql[2][2][6];
#pragma unroll
    for (int mi = 0; mi < 2; mi++)
#pragma unroll
        for (int p = 0; p < 2; p++)
#pragma unroll
            for (int j = 0; j < 6; j++) ql[mi][p][j] = INFINITY;

    float acc[2][4][4];
#pragma unroll
    for (int mi = 0; mi < 2; mi++)
#pragma unroll
        for (int ni = 0; ni < 4; ni++)
#pragma unroll
            for (int r = 0; r < 4; r++) acc[mi][ni][r] = 0.f;

    // ---- main loop: 128 tiles, 8 fully-unrolled stages per tile ----
    // gg = nt*8 + s ; slot(gg) = gg&3 = s&3 (8 ≡ 0 mod 4) ; Achunk = s.
    // Prefetch gg+3: slot (s+3)&3, stage (s+3)&7, tile nt + ((s+3)>>3).
#pragma unroll 1
    for (int nt = 0; nt < NTILES; nt++) {
        const int mb = nt & 1;
        const int n0 = nt * NT;
        if (tid < 128) m2s[mb * 128 + tid] = g_m2[n0 + tid];

#pragma unroll
        for (int s = 0; s < 8; s++) {
            CP_WAIT(2);
            __syncthreads();

            const uint32_t bbuf = bOff + (s & 3) * 16384;       // compile-time offset
            const uint32_t abuf = aOff + s * 16384;             // compile-time offset
#pragma unroll
            for (int kk = 0; kk < 64; kk += 16) {
                uint32_t a[2][4], bf[4][2];
#pragma unroll
                for (int mi = 0; mi < 2; mi++) {
                    uint32_t ad = abuf + (uint32_t)SWZ128(((aRow + mi * 16) * 128 + (kk + aColSel) * 2));
                    LDSM4(a[mi][0], a[mi][1], a[mi][2], a[mi][3], ad);
                }
#pragma unroll
                for (int jp = 0; jp < 2; jp++) {
                    uint32_t bd = bbuf + (uint32_t)SWZ128(((bRow + jp * 16) * 128 + (kk + bColSel) * 2));
                    LDSM4(bf[2 * jp][0], bf[2 * jp][1], bf[2 * jp + 1][0], bf[2 * jp + 1][1], bd);
                }
#pragma unroll
                for (int mi = 0; mi < 2; mi++)
#pragma unroll
                    for (int ni = 0; ni < 4; ni++)
                        MMA16816(acc[mi][ni], a[mi], bf[ni][0], bf[ni][1]);
            }

            // prefetch stage gg+3 (compile-time slot/stage; tile carry is compile-time on s)
            {
                const int nt3 = nt + ((s + 3) >> 3);
                if (nt3 < NTILES)
                    b_stage(bOff, (s + 3) & 3, nt3 * NT, (s + 3) & 7, tid);
            }
            CP_COMMIT();

            if (s == 7) {
                // in-register epilogue: 16 distances into 4 running lists
#pragma unroll
                for (int mi = 0; mi < 2; mi++)
#pragma unroll
                    for (int ni = 0; ni < 4; ni++) {
                        const int col = wn * 32 + ni * 8 + 2 * qd;
                        const float m20 = m2s[mb * 128 + col];
                        const float m21 = m2s[mb * 128 + col + 1];
                        insert6a(fmaxf(fmaf(-2.f, acc[mi][ni][0], x2v[mi][0] + m20), 0.f), ql[mi][0]);
                        insert6a(fmaxf(fmaf(-2.f, acc[mi][ni][1], x2v[mi][0] + m21), 0.f), ql[mi][0]);
                        insert6a(fmaxf(fmaf(-2.f, acc[mi][ni][2], x2v[mi][1] + m20), 0.f), ql[mi][1]);
                        insert6a(fmaxf(fmaf(-2.f, acc[mi][ni][3], x2v[mi][1] + m21), 0.f), ql[mi][1]);
                        acc[mi][ni][0] = 0.f; acc[mi][ni][1] = 0.f;
                        acc[mi][ni][2] = 0.f; acc[mi][ni][3] = 0.f;
                    }
            }
        }
    }

    // ---- quad merge (same 4 rows within a quad), snapshot-before-insert
#pragma unroll
    for (int off = 2; off > 0; off >>= 1) {
#pragma unroll
        for (int mi = 0; mi < 2; mi++)
#pragma unroll
            for (int p = 0; p < 2; p++) {
                float t[6];
#pragma unroll
                for (int j = 0; j < 6; j++)
                    t[j] = __shfl_down_sync(0xffffffffu, ql[mi][p][j], off, 4);
#pragma unroll
                for (int j = 0; j < 6; j++) insert6a(t[j], ql[mi][p]);
            }
    }

    // ---- cross-warp merge staging: 4 N-warps per row, 6 values each
    if (qd == 0) {
#pragma unroll
        for (int mi = 0; mi < 2; mi++)
#pragma unroll
            for (int p = 0; p < 2; p++) {
                int r = wm * 32 + mi * 16 + g + p * 8;
#pragma unroll
                for (int j = 0; j < 6; j++)
                    stage[r * 24 + wn * 6 + j] = ql[mi][p][j];
            }
    }
    __syncthreads();

    float part = 0.f;
    if (tid < 128) {
        float f[6] = {INFINITY, INFINITY, INFINITY, INFINITY, INFINITY, INFINITY};
        const float* sr = stage + tid * 24;
#pragma unroll
        for (int i = 0; i < 24; i++) insert6a(sr[i], f);
        float rv = rptr[0];
        float r2 = rv * rv;
        part = fmaxf(f[0] - r2, 0.f) + fmaxf(f[1] - r2, 0.f) + fmaxf(f[2] - r2, 0.f)
             + fmaxf(r2 - f[3] - ALPHA_C, 0.f) + fmaxf(r2 - f[4] - ALPHA_C, 0.f)
             + fmaxf(r2 - f[5] - ALPHA_C, 0.f);
    }
    __syncthreads();
    float* red = stage;
    red[tid] = part;
    __syncthreads();
#pragma unroll
    for (int o = 256; o > 0; o >>= 1) {
        if (tid < o) red[tid] += red[tid + o];
        __syncthreads();
    }
    if (tid == 0) g_part[blockIdx.x] = red[0];
}

// Deterministic final reduction
__global__ void finalize_loss(float* __restrict__ out) {
    __shared__ float s[128];
    int t = threadIdx.x;
    s[t] = g_part[t];
    __syncthreads();
#pragma unroll
    for (int o = 64; o > 0; o >>= 1) {
        if (t < o) s[t] += s[t + o];
        __syncthreads();
    }
    if (t == 0) out[0] = s[0] * (1.0f / (49152.0f * NU_C));
}

// ---------------- launch ----------------
extern "C" void kernel_launch(void* const* d_in, const int* in_sizes, int n_in,
                              void* d_out, int out_size) {
    (void)in_sizes; (void)n_in; (void)out_size;
    const float* phi = (const float*)d_in[0];
    const float* mem = (const float*)d_in[1];
    const float* r   = (const float*)d_in[2];
    float* out = (float*)d_out;

    cudaFuncSetAttribute(knn_gemm, cudaFuncAttributeMaxDynamicSharedMemorySize, SMEM_BYTES);

    prep_phi<<<dim3(128, 16, 4), dim3(32, 8)>>>(phi);
    prep_x2<<<MDIM / 256, 256>>>(phi);
    prep_mem<<<NDIM / 8, 256>>>(mem);
    knn_gemm<<<MDIM / MT, 512, SMEM_BYTES>>>(r);
    finalize_loss<<<1, 128>>>(out);
}